// round 13
// baseline (speedup 1.0000x reference)
#include <cuda_runtime.h>
#include <cuda_bf16.h>
#include <mma.h>
#include <math.h>
#include <stdint.h>

using namespace nvcuda;

#define BN_SCALE_F 0.9999950000374996f

// ---------------- static scratch ----------------
__device__ float g_pad[93007872];
__device__ float g_act[308281344];
__device__ float g_feat[24 * 8192];
__device__ float g_fc6[24 * 4096];
__device__ float g_fc7[24 * 4096];
__device__ float g_norm[24];
__device__ float g_cost[144];
__device__ unsigned short g_wh[27654144];  // bf16 hi planes: conv2..conv5b, then conv1(Kpad 96)
__device__ unsigned short g_wl[27654144];  // bf16 lo planes

// ---------------- helpers ----------------
__device__ __forceinline__ unsigned pack_split(float v) {
    float hf = __uint_as_float(__float_as_uint(v) & 0xFFFF0000u);
    unsigned hi = __float_as_uint(hf) >> 16;
    float r = v - hf;
    unsigned lo = __float_as_uint(r) >> 16;
    return hi | (lo << 16);
}
__device__ __forceinline__ uint32_t smem_u32(const void* p) {
    uint32_t a;
    asm("{ .reg .u64 t; cvta.to.shared.u64 t, %1; cvt.u32.u64 %0, t; }" : "=r"(a) : "l"(p));
    return a;
}
__device__ __forceinline__ void cp_async8(uint32_t dst, const void* src) {
    asm volatile("cp.async.ca.shared.global [%0], [%1], 8;" :: "r"(dst), "l"(src));
}
__device__ __forceinline__ void cp_async4(uint32_t dst, const void* src) {
    asm volatile("cp.async.ca.shared.global [%0], [%1], 4;" :: "r"(dst), "l"(src));
}

// ---------------- input rearrange + pad -> packed split words ----------------
__global__ void rearrange_pad_kernel(const float* __restrict__ sup, const float* __restrict__ qry,
                                     unsigned* __restrict__ out)
{
    const int plane = blockIdx.z;          // clip*3 + c
    const int dz = blockIdx.y;             // 0..17
    const int clip = plane / 3;
    const int c = plane - clip * 3;
    const int s = blockIdx.x * blockDim.x + threadIdx.x;
    const int HWp = 114 * 114;
    if (s >= HWp) return;
    int hy = s / 114;
    int wx = s - hy * 114;
    float val = 0.0f;
    if (dz >= 1 && dz <= 16 && hy >= 1 && hy <= 112 && wx >= 1 && wx <= 112) {
        int tt = dz - 1, h = hy - 1, w = wx - 1;
        const float* src = (clip < 12) ? sup : qry;
        int cc = (clip < 12) ? clip : clip - 12;
        long addr = ((((long)cc * 16 + tt) * 3 + c) * 112 + h) * 112 + w;
        val = src[addr];
    }
    out[((long)plane * 18 + dz) * HWp + s] = pack_split(val);
}

// split weights fp32 -> separate bf16 hi/lo planes, optional K padding
__global__ void wsplit_kernel(const float* __restrict__ w, unsigned short* __restrict__ hi,
                              unsigned short* __restrict__ lo, int Ktrue, int Kpad, int total)
{
    int idx = blockIdx.x * blockDim.x + threadIdx.x;
    if (idx >= total) return;
    int m = idx / Kpad, k = idx - m * Kpad;
    float v = (k < Ktrue) ? w[m * Ktrue + k] : 0.0f;
    float hf = __uint_as_float(__float_as_uint(v) & 0xFFFF0000u);
    hi[idx] = (unsigned short)(__float_as_uint(v) >> 16);
    lo[idx] = (unsigned short)(__float_as_uint(v - hf) >> 16);
}

// ---------------- wmma split-bf16 conv (all conv layers) ----------------
// GEMM: M=Cout (BM/tile), N=spatial (128/tile), K chunks of 32.
// A (weights): dense bf16 hi/lo planes -> cp.async(8B).
// B (acts): packed split words -> cp.async(4B) into staging, smem split pass.
template<int BM>
__global__ __launch_bounds__(256, 2)
void conv_tc(const unsigned short* __restrict__ wh, const unsigned short* __restrict__ wl,
             const unsigned* __restrict__ inp, float* __restrict__ out,
             const float* __restrict__ bias, float scale,
             int Cin, int D, int H, int W, int Ktrue, int K, int Cout, int Ntotal)
{
    constexpr int ASZ  = BM * 80;         // bytes per A plane (stride 40 bf16)
    constexpr int BHI  = 2 * ASZ;
    constexpr int BLO  = BHI + 10240;
    constexpr int TCB  = BHI + 20480;     // bytes per main buffer
    constexpr int STG  = 2 * TCB;         // staging offset (single buffer, 128 x 132B)
    constexpr int AI   = BM / 32;
    extern __shared__ char dsm[];
    char* albase = (char*)(((uintptr_t)dsm + 1023) & ~(uintptr_t)1023);
    const uint32_t sbase = smem_u32(albase);
    const uint32_t stgb = sbase + STG;

    const int Hp = H + 2, Wp = W + 2;
    const int HWp = Hp * Wp;
    const int chanStride = (D + 2) * HWp;
    const int HW = H * W;
    const int DHW = D * HW;

    const int t = threadIdx.x;
    const int wid = t >> 5;
    const int ntile = blockIdx.x;
    const int mtile = blockIdx.y;

    // ---- A: cp.async dense copy ----
    auto CPA = [&](int bufIdx, int k0) {
        uint32_t dst0 = sbase + bufIdx * TCB;
#pragma unroll
        for (int i = 0; i < BM / 16; ++i) {
            int c = t + 256 * i;
            int plane = c / (BM * 8);
            int rem = c - plane * (BM * 8);
            int row = rem >> 3, q = rem & 7;
            const unsigned short* src = (plane ? wl : wh) + (size_t)(mtile * BM + row) * K + k0 + q * 4;
            cp_async8(dst0 + plane * ASZ + row * 80 + q * 8, src);
        }
    };

    // ---- B gather mapping: nl = lane->n, kb = warp->4 k ----
    const int nl = t & 31;
    const int kb = (t >> 5) << 2;
    int nbB[4];
#pragma unroll
    for (int i = 0; i < 4; ++i) {
        int n = ntile * 128 + i * 32 + nl;
        if (n >= Ntotal) n = Ntotal - 1;
        int b = n / DHW;
        int rem = n - b * DHW;
        int d = rem / HW;
        int r2 = rem - d * HW;
        int h = r2 / W;
        int w = r2 - h * W;
        nbB[i] = b * Cin * chanStride + d * HWp + h * Wp + w;
    }

    // B: cp.async packed words into staging (row stride 132 B -> conflict-free readback)
    auto CPB = [&](int k0) {
        int ko[4];
#pragma unroll
        for (int j = 0; j < 4; ++j) {
            int k = k0 + kb + j;
            if (k >= Ktrue) k = 0;
            int ci = k / 27, r_ = k - ci * 27;
            int kd = r_ / 9; r_ -= kd * 9;
            int kh = r_ / 3, kw = r_ - kh * 3;
            ko[j] = ci * chanStride + kd * HWp + kh * Wp + kw;
        }
#pragma unroll
        for (int i = 0; i < 4; ++i)
#pragma unroll
            for (int j = 0; j < 4; ++j)
                cp_async4(stgb + (i * 32 + nl) * 132 + (kb + j) * 4, inp + nbB[i] + ko[j]);
    };

    // split staging -> hi/lo planes of buffer sb
    auto SPLITB = [&](char* sb) {
#pragma unroll
        for (int i = 0; i < 4; ++i) {
            uint32_t w0 = *(uint32_t*)(albase + STG + (i * 32 + nl) * 132 + (kb + 0) * 4);
            uint32_t w1 = *(uint32_t*)(albase + STG + (i * 32 + nl) * 132 + (kb + 1) * 4);
            uint32_t w2 = *(uint32_t*)(albase + STG + (i * 32 + nl) * 132 + (kb + 2) * 4);
            uint32_t w3 = *(uint32_t*)(albase + STG + (i * 32 + nl) * 132 + (kb + 3) * 4);
            uint32_t bhi, blo;
            int off = (i * 32 + nl) * 80 + kb * 2;
            asm("prmt.b32 %0, %1, %2, 0x5410;" : "=r"(bhi) : "r"(w0), "r"(w1));
            asm("prmt.b32 %0, %1, %2, 0x7632;" : "=r"(blo) : "r"(w0), "r"(w1));
            *(uint32_t*)(sb + BHI + off) = bhi;
            *(uint32_t*)(sb + BLO + off) = blo;
            asm("prmt.b32 %0, %1, %2, 0x5410;" : "=r"(bhi) : "r"(w2), "r"(w3));
            asm("prmt.b32 %0, %1, %2, 0x7632;" : "=r"(blo) : "r"(w2), "r"(w3));
            *(uint32_t*)(sb + BHI + off + 4) = bhi;
            *(uint32_t*)(sb + BLO + off + 4) = blo;
        }
    };

    // ---- accumulators: warp (wm, wn) owns (BM/2) x 32 ----
    const int wm = wid >> 2;
    const int wn = wid & 3;
    wmma::fragment<wmma::accumulator, 16, 16, 16, float> acc[AI][2];
#pragma unroll
    for (int i = 0; i < AI; ++i)
#pragma unroll
        for (int j = 0; j < 2; ++j) wmma::fill_fragment(acc[i][j], 0.0f);

    auto COMPUTE = [&](char* sb) {
        const __nv_bfloat16* Ahi = (const __nv_bfloat16*)(sb);
        const __nv_bfloat16* Alo = (const __nv_bfloat16*)(sb + ASZ);
        const __nv_bfloat16* Bhi = (const __nv_bfloat16*)(sb + BHI);
        const __nv_bfloat16* Blo = (const __nv_bfloat16*)(sb + BLO);
#pragma unroll
        for (int ks = 0; ks < 2; ++ks) {
            wmma::fragment<wmma::matrix_b, 16, 16, 16, __nv_bfloat16, wmma::col_major> bh[2], bl[2];
#pragma unroll
            for (int j = 0; j < 2; ++j) {
                const int co = (wn * 32 + j * 16) * 40 + ks * 16;
                wmma::load_matrix_sync(bh[j], Bhi + co, 40);
                wmma::load_matrix_sync(bl[j], Blo + co, 40);
            }
#pragma unroll
            for (int i = 0; i < AI; ++i) {
                const int ro = (wm * (BM / 2) + i * 16) * 40 + ks * 16;
                wmma::fragment<wmma::matrix_a, 16, 16, 16, __nv_bfloat16, wmma::row_major> ah, al;
                wmma::load_matrix_sync(ah, Ahi + ro, 40);
                wmma::load_matrix_sync(al, Alo + ro, 40);
#pragma unroll
                for (int j = 0; j < 2; ++j) {
                    wmma::mma_sync(acc[i][j], ah, bh[j], acc[i][j]);
                    wmma::mma_sync(acc[i][j], ah, bl[j], acc[i][j]);
                    wmma::mma_sync(acc[i][j], al, bh[j], acc[i][j]);
                }
            }
        }
    };

    const int KT = K / 32;
    // prologue: fill buffer 0
    CPA(0, 0);
    CPB(0);
    asm volatile("cp.async.commit_group;");
    asm volatile("cp.async.wait_group 0;" ::: "memory");
    __syncthreads();
    SPLITB(albase);
    __syncthreads();

    for (int kc = 0; kc < KT; ++kc) {
        char* cur = albase + (kc & 1) * TCB;
        char* nxt = albase + ((kc & 1) ^ 1) * TCB;
        if (kc + 1 < KT) {
            CPA((kc & 1) ^ 1, (kc + 1) * 32);
            CPB((kc + 1) * 32);
            asm volatile("cp.async.commit_group;");
        }
        COMPUTE(cur);
        if (kc + 1 < KT) {
            asm volatile("cp.async.wait_group 0;" ::: "memory");
            __syncthreads();
            SPLITB(nxt);
        }
        __syncthreads();
    }

    // ---- epilogue: stage BMx128 fp32 in smem, coalesced scatter ----
    float* stage = (float*)albase;
#pragma unroll
    for (int i = 0; i < AI; ++i)
#pragma unroll
        for (int j = 0; j < 2; ++j)
            wmma::store_matrix_sync(stage + (wm * (BM / 2) + i * 16) * 132 + (wn * 32 + j * 16),
                                    acc[i][j], 132, wmma::mem_row_major);
    __syncthreads();
    {
        const int jn = t & 127, rh = t >> 7;
        const int n = ntile * 128 + jn;
        if (n < Ntotal) {
            int b = n / DHW, rem = n - b * DHW;
            size_t obase = ((size_t)b * Cout) * DHW + rem;
#pragma unroll 4
            for (int i = 0; i < BM / 2; ++i) {
                int m = rh * (BM / 2) + i;
                int mg = mtile * BM + m;
                float v = scale * (stage[m * 132 + jn] + bias[mg]);
                out[obase + (size_t)mg * DHW] = fmaxf(v, 0.0f);
            }
        }
    }
}

// ---------------- maxpool + pad (grid: x=HWp, y=Dp, z=plane) ----------------
__global__ void pool_pad_kernel(const float* __restrict__ in, float* __restrict__ out,
                                int D, int H, int W,
                                int kd, int kh, int kw, int sd, int sh, int sw,
                                int pd, int ph, int pw,
                                int Do, int Ho, int Wo, int cp, int split)
{
    const int plane = blockIdx.z;
    const int z = blockIdx.y;
    const int Hp = Ho + 2 * cp, Wp = Wo + 2 * cp, Dp = Do + 2 * cp;
    const int HWp = Hp * Wp;
    const int s = blockIdx.x * blockDim.x + threadIdx.x;
    if (s >= HWp) return;
    int y = s / Wp;
    int x = s - y * Wp;
    float v = 0.0f;
    int od = z - cp, oh = y - cp, ow = x - cp;
    if (od >= 0 && od < Do && oh >= 0 && oh < Ho && ow >= 0 && ow < Wo) {
        float m = -3.4e38f;
        int id0 = od * sd - pd, ih0 = oh * sh - ph, iw0 = ow * sw - pw;
        const float* base = in + (long)plane * D * H * W;
        for (int a = 0; a < kd; ++a) {
            int id = id0 + a;
            if (id < 0 || id >= D) continue;
            for (int e = 0; e < kh; ++e) {
                int ih = ih0 + e;
                if (ih < 0 || ih >= H) continue;
                for (int f = 0; f < kw; ++f) {
                    int iw = iw0 + f;
                    if (iw < 0 || iw >= W) continue;
                    float q = base[(id * H + ih) * W + iw];
                    m = fmaxf(m, q);
                }
            }
        }
        v = m;
    }
    long oi = ((long)plane * Dp + z) * HWp + s;
    if (split) ((unsigned*)out)[oi] = pack_split(v);
    else out[oi] = v;
}

// ---------------- tiled FC ----------------
__global__ __launch_bounds__(256)
void fc_tile_kernel(const float* __restrict__ x, const float* __restrict__ W,
                    const float* __restrict__ b, float* __restrict__ y,
                    int K, int M, float scale)
{
    __shared__ float xs[24][260];
    const int warp = threadIdx.x >> 5, lane = threadIdx.x & 31;
    const int m = blockIdx.x * 8 + warp;
    float acc[24];
#pragma unroll
    for (int n = 0; n < 24; ++n) acc[n] = 0.0f;

    const float* wr = W + (size_t)m * K;
    for (int k0 = 0; k0 < K; k0 += 256) {
        __syncthreads();
        for (int i = threadIdx.x; i < 24 * 64; i += 256) {
            int n = i / 64, kq = i - n * 64;
            *(float4*)&xs[n][kq * 4] = *(const float4*)(x + (size_t)n * K + k0 + kq * 4);
        }
        __syncthreads();
#pragma unroll 2
        for (int kq = lane; kq < 64; kq += 32) {
            float4 w4 = *(const float4*)(wr + k0 + kq * 4);
#pragma unroll
            for (int n = 0; n < 24; ++n) {
                float4 x4 = *(const float4*)&xs[n][kq * 4];
                acc[n] += w4.x * x4.x + w4.y * x4.y + w4.z * x4.z + w4.w * x4.w;
            }
        }
    }
#pragma unroll
    for (int n = 0; n < 24; ++n) {
#pragma unroll
        for (int o = 16; o > 0; o >>= 1)
            acc[n] += __shfl_xor_sync(0xFFFFFFFFu, acc[n], o);
    }
    if (lane == 0) {
#pragma unroll
        for (int n = 0; n < 24; ++n) {
            float v = scale * (acc[n] + b[m]);
            y[(size_t)n * M + m] = fmaxf(v, 0.0f);
        }
    }
}

__global__ void rownorm_kernel(const float* __restrict__ x, float* __restrict__ nrm, int K)
{
    int row = blockIdx.x;
    float s = 0.0f;
    for (int k = threadIdx.x; k < K; k += 128) {
        float v = x[(size_t)row * K + k];
        s += v * v;
    }
    __shared__ float sm[128];
    sm[threadIdx.x] = s;
    __syncthreads();
    for (int o = 64; o > 0; o >>= 1) {
        if (threadIdx.x < o) sm[threadIdx.x] += sm[threadIdx.x + o];
        __syncthreads();
    }
    if (threadIdx.x == 0) nrm[row] = sqrtf(sm[0]);
}

__global__ void cost_kernel(const float* __restrict__ feat, const float* __restrict__ nrm,
                            float* __restrict__ cost)
{
    int bi = blockIdx.x;
    int j = bi & 3, t2 = bi >> 2;
    int i = t2 & 3, t3 = t2 >> 2;
    int s = t3 % 3, q = t3 / 3;
    int qrow = 12 + q * 4 + i;
    int srow = s * 4 + j;
    const float* a = feat + (size_t)qrow * 4096;
    const float* c = feat + (size_t)srow * 4096;
    float pr = 0.0f;
    for (int k = threadIdx.x; k < 4096; k += 128) pr += a[k] * c[k];
    __shared__ float sm[128];
    sm[threadIdx.x] = pr;
    __syncthreads();
    for (int o = 64; o > 0; o >>= 1) {
        if (threadIdx.x < o) sm[threadIdx.x] += sm[threadIdx.x + o];
        __syncthreads();
    }
    if (threadIdx.x == 0)
        cost[bi] = 1.0f - sm[0] / ((nrm[qrow] + 1e-8f) * (nrm[srow] + 1e-8f));
}

__global__ void sinkhorn_kernel(const float* __restrict__ cost, float* __restrict__ outp)
{
    int t = threadIdx.x;
    if (t >= 9) return;
    float sem[16], Km[16];
    for (int i = 0; i < 4; ++i)
        for (int j = 0; j < 4; ++j) {
            float sc = cost[t * 16 + i * 4 + j];
            float ti = i * 0.25f, tj = j * 0.25f;
            float d2 = (ti - tj) * (ti - tj);
            float pos = expf(-1.0f / (d2 + 1.0f));
            sem[i * 4 + j] = sc;
            Km[i * 4 + j] = expf(-7.0f * (sc + 0.4f * pos));
        }
    float u[4] = {0.25f, 0.25f, 0.25f, 0.25f}, v[4];
    for (int it = 0; it < 100; ++it) {
        for (int j = 0; j < 4; ++j) {
            float s = 1e-9f;
            for (int i = 0; i < 4; ++i) s += Km[i * 4 + j] * u[i];
            v[j] = 0.25f / s;
        }
        for (int i = 0; i < 4; ++i) {
            float s = 1e-9f;
            for (int j = 0; j < 4; ++j) s += Km[i * 4 + j] * v[j];
            u[i] = 0.25f / s;
        }
    }
    for (int j = 0; j < 4; ++j) {
        float s = 1e-9f;
        for (int i = 0; i < 4; ++i) s += Km[i * 4 + j] * u[i];
        v[j] = 0.25f / s;
    }
    float tr = 0.0f;
    for (int i = 0; i < 4; ++i)
        for (int j = 0; j < 4; ++j)
            tr += u[i] * Km[i * 4 + j] * v[j] * sem[i * 4 + j];
    outp[t] = -tr;
}

// ---------------- driver ----------------
static inline int cdiv_i(long a, long b) { return (int)((a + b - 1) / b); }

extern "C" void kernel_launch(void* const* d_in, const int* in_sizes, int n_in,
                              void* d_out, int out_size)
{
    const float* sup  = (const float*)d_in[0];
    const float* qry  = (const float*)d_in[1];
    const float* w1   = (const float*)d_in[2];
    const float* b1   = (const float*)d_in[3];
    const float* w2   = (const float*)d_in[4];
    const float* b2   = (const float*)d_in[5];
    const float* w3a  = (const float*)d_in[6];
    const float* b3a  = (const float*)d_in[7];
    const float* w3b  = (const float*)d_in[8];
    const float* b3b  = (const float*)d_in[9];
    const float* w4a  = (const float*)d_in[10];
    const float* b4a  = (const float*)d_in[11];
    const float* w4b  = (const float*)d_in[12];
    const float* b4b  = (const float*)d_in[13];
    const float* w5a  = (const float*)d_in[14];
    const float* b5a  = (const float*)d_in[15];
    const float* w5b  = (const float*)d_in[16];
    const float* b5b  = (const float*)d_in[17];
    const float* fw6  = (const float*)d_in[18];
    const float* fb6  = (const float*)d_in[19];
    const float* fw7  = (const float*)d_in[20];
    const float* fb7  = (const float*)d_in[21];

    float *pad, *act, *feat, *fc6o, *fc7o, *nrm, *cst;
    unsigned short *wh, *wl;
    cudaGetSymbolAddress((void**)&pad,  g_pad);
    cudaGetSymbolAddress((void**)&act,  g_act);
    cudaGetSymbolAddress((void**)&feat, g_feat);
    cudaGetSymbolAddress((void**)&fc6o, g_fc6);
    cudaGetSymbolAddress((void**)&fc7o, g_fc7);
    cudaGetSymbolAddress((void**)&nrm,  g_norm);
    cudaGetSymbolAddress((void**)&cst,  g_cost);
    cudaGetSymbolAddress((void**)&wh,   g_wh);
    cudaGetSymbolAddress((void**)&wl,   g_wl);

    const float SC = BN_SCALE_F;
    const int TC_SMEM128 = 2 * (2 * 128 * 80 + 20480) + 16896 + 1024;  // ~99.8 KB
    const int TC_SMEM64  = 2 * (2 * 64 * 80 + 20480) + 16896 + 1024;   // ~79.3 KB
    cudaFuncSetAttribute(conv_tc<128>, cudaFuncAttributeMaxDynamicSharedMemorySize, TC_SMEM128);
    cudaFuncSetAttribute(conv_tc<64>,  cudaFuncAttributeMaxDynamicSharedMemorySize, TC_SMEM64);

    // weight plane offsets (elements)
    const long O2 = 0, O3A = 221184, O3B = 1105920, O4A = 2875392;
    const long O4B = 6414336, O5A = 13492224, O5B = 20570112, O1 = 27648000;

    // launch order crafted so the 6th launch (ncu -s 5 -c 1) is conv2's conv_tc<128>
    rearrange_pad_kernel<<<dim3(cdiv_i(114 * 114, 256), 18, 72), 256>>>(sup, qry, (unsigned*)pad);  // 1
    wsplit_kernel<<<cdiv_i(6144, 256), 256>>>(w1, wh + O1, wl + O1, 81, 96, 6144);                  // 2
    conv_tc<64><<<dim3(37632, 1), 256, TC_SMEM64>>>(wh + O1, wl + O1, (unsigned*)pad, act, b1, SC,  // 3
                                                    3, 16, 112, 112, 81, 96, 64, 4816896);
    pool_pad_kernel<<<dim3(cdiv_i(58 * 58, 256), 18, 24 * 64), 256>>>(                              // 4
        act, pad, 16, 112, 112, 1, 2, 2, 1, 2, 2, 0, 0, 0, 16, 56, 56, 1, 1);
    wsplit_kernel<<<cdiv_i(221184, 256), 256>>>(w2, wh + O2, wl + O2, 1728, 1728, 221184);          // 5
    conv_tc<128><<<dim3(9408, 1), 256, TC_SMEM128>>>(wh + O2, wl + O2, (unsigned*)pad, act, b2, SC, // 6 <- ncu
                                                     64, 16, 56, 56, 1728, 1728, 128, 1204224);
    pool_pad_kernel<<<dim3(cdiv_i(30 * 30, 256), 10, 24 * 128), 256>>>(
        act, pad, 16, 56, 56, 2, 2, 2, 2, 2, 2, 0, 0, 0, 8, 28, 28, 1, 1);
    wsplit_kernel<<<cdiv_i(884736, 256), 256>>>(w3a, wh + O3A, wl + O3A, 3456, 3456, 884736);
    conv_tc<128><<<dim3(1176, 2), 256, TC_SMEM128>>>(wh + O3A, wl + O3A, (unsigned*)pad, act, b3a, 1.0f,
                                                     128, 8, 28, 28, 3456, 3456, 256, 150528);
    pool_pad_kernel<<<dim3(cdiv_i(30 * 30, 256), 10, 24 * 256), 256>>>(
        act, pad, 8, 28, 28, 1, 1, 1, 1, 1, 1, 0, 0, 0, 8, 28, 28, 1, 1);
    wsplit_kernel<<<cdiv_i(1769472, 256), 256>>>(w3b, wh + O3B, wl + O3B, 6912, 6912, 1769472);
    conv_tc<128><<<dim3(1176, 2), 256, TC_SMEM128>>>(wh + O3B, wl + O3B, (unsigned*)pad, act, b3b, SC,
                                                     256, 8, 28, 28, 6912, 6912, 256, 150528);
    pool_pad_kernel<<<dim3(1, 6, 24 * 256), 256>>>(
        act, pad, 8, 28, 28, 2, 2, 2, 2, 2, 2, 0, 0, 0, 4, 14, 14, 1, 1);
    wsplit_kernel<<<cdiv_i(3538944, 256), 256>>>(w4a, wh + O4A, wl + O4A, 6912, 6912, 3538944);
    conv_tc<128><<<dim3(147, 4), 256, TC_SMEM128>>>(wh + O4A, wl + O4A, (unsigned*)pad, act, b4a, 1.0f,
                                                    256, 4, 14, 14, 6912, 6912, 512, 18816);
    pool_pad_kernel<<<dim3(1, 6, 24 * 512), 256>>>(
        act, pad, 4, 14, 14, 1, 1, 1, 1, 1, 1, 0, 0, 0, 4, 14, 14, 1, 1);
    wsplit_kernel<<<cdiv_i(7077888, 256), 256>>>(w4b, wh + O4B, wl + O4B, 13824, 13824, 7077888);
    conv_tc<128><<<dim3(147, 4), 256, TC_SMEM128>>>(wh + O4B, wl + O4B, (unsigned*)pad, act, b4b, SC,
                                                    512, 4, 14, 14, 13824, 13824, 512, 18816);
    pool_pad_kernel<<<dim3(1, 4, 24 * 512), 256>>>(
        act, pad, 4, 14, 14, 2, 2, 2, 2, 2, 2, 0, 0, 0, 2, 7, 7, 1, 1);
    wsplit_kernel<<<cdiv_i(7077888, 256), 256>>>(w5a, wh + O5A, wl + O5A, 13824, 13824, 7077888);
    // conv5a/b: BM=64 -> 19x8 = 152 blocks (full wave vs 76)
    conv_tc<64><<<dim3(19, 8), 256, TC_SMEM64>>>(wh + O5A, wl + O5A, (unsigned*)pad, act, b5a, 1.0f,
                                                 512, 2, 7, 7, 13824, 13824, 512, 2352);
    pool_pad_kernel<<<dim3(1, 4, 24 * 512), 256>>>(
        act, pad, 2, 7, 7, 1, 1, 1, 1, 1, 1, 0, 0, 0, 2, 7, 7, 1, 1);
    wsplit_kernel<<<cdiv_i(7077888, 256), 256>>>(w5b, wh + O5B, wl + O5B, 13824, 13824, 7077888);
    conv_tc<64><<<dim3(19, 8), 256, TC_SMEM64>>>(wh + O5B, wl + O5B, (unsigned*)pad, act, b5b, SC,
                                                 512, 2, 7, 7, 13824, 13824, 512, 2352);
    // pool5 -> features (fp32)
    pool_pad_kernel<<<dim3(1, 1, 24 * 512), 256>>>(
        act, feat, 2, 7, 7, 2, 2, 2, 2, 2, 2, 0, 1, 1, 1, 4, 4, 0, 0);
    // fc6, fc7
    fc_tile_kernel<<<512, 256>>>(feat, fw6, fb6, fc6o, 8192, 4096, SC);
    fc_tile_kernel<<<512, 256>>>(fc6o, fw7, fb7, fc7o, 4096, 4096, SC);
    // head
    rownorm_kernel<<<24, 128>>>(fc7o, nrm, 4096);
    cost_kernel<<<144, 128>>>(fc7o, nrm, cst);
    sinkhorn_kernel<<<1, 32>>>(cst, (float*)d_out);
}

// round 15
// speedup vs baseline: 1.1750x; 1.1750x over previous
#include <cuda_runtime.h>
#include <cuda_bf16.h>
#include <mma.h>
#include <math.h>
#include <stdint.h>

using namespace nvcuda;

#define BN_SCALE_F 0.9999950000374996f

// ---------------- static scratch ----------------
__device__ float g_pad[93007872];
__device__ float g_act[308281344];
__device__ float g_feat[24 * 8192];
__device__ float g_fc6[24 * 4096];
__device__ float g_fc7[24 * 4096];
__device__ float g_norm[24];
__device__ float g_cost[144];
__device__ unsigned short g_wh[27654144];  // bf16 hi planes: conv2..conv5b, then conv1(Kpad 96)
__device__ unsigned short g_wl[27654144];  // bf16 lo planes

// ---------------- helpers ----------------
__device__ __forceinline__ unsigned pack_split(float v) {
    float hf = __uint_as_float(__float_as_uint(v) & 0xFFFF0000u);
    unsigned hi = __float_as_uint(hf) >> 16;
    float r = v - hf;
    unsigned lo = __float_as_uint(r) >> 16;
    return hi | (lo << 16);
}
__device__ __forceinline__ uint32_t smem_u32(const void* p) {
    uint32_t a;
    asm("{ .reg .u64 t; cvta.to.shared.u64 t, %1; cvt.u32.u64 %0, t; }" : "=r"(a) : "l"(p));
    return a;
}
__device__ __forceinline__ void cp_async8(uint32_t dst, const void* src) {
    asm volatile("cp.async.ca.shared.global [%0], [%1], 8;" :: "r"(dst), "l"(src));
}

// ---------------- input rearrange + pad -> packed split words ----------------
__global__ void rearrange_pad_kernel(const float* __restrict__ sup, const float* __restrict__ qry,
                                     unsigned* __restrict__ out)
{
    const int plane = blockIdx.z;          // clip*3 + c
    const int dz = blockIdx.y;             // 0..17
    const int clip = plane / 3;
    const int c = plane - clip * 3;
    const int s = blockIdx.x * blockDim.x + threadIdx.x;
    const int HWp = 114 * 114;
    if (s >= HWp) return;
    int hy = s / 114;
    int wx = s - hy * 114;
    float val = 0.0f;
    if (dz >= 1 && dz <= 16 && hy >= 1 && hy <= 112 && wx >= 1 && wx <= 112) {
        int tt = dz - 1, h = hy - 1, w = wx - 1;
        const float* src = (clip < 12) ? sup : qry;
        int cc = (clip < 12) ? clip : clip - 12;
        long addr = ((((long)cc * 16 + tt) * 3 + c) * 112 + h) * 112 + w;
        val = src[addr];
    }
    out[((long)plane * 18 + dz) * HWp + s] = pack_split(val);
}

// split weights fp32 -> separate bf16 hi/lo planes, optional K padding
__global__ void wsplit_kernel(const float* __restrict__ w, unsigned short* __restrict__ hi,
                              unsigned short* __restrict__ lo, int Ktrue, int Kpad, int total)
{
    int idx = blockIdx.x * blockDim.x + threadIdx.x;
    if (idx >= total) return;
    int m = idx / Kpad, k = idx - m * Kpad;
    float v = (k < Ktrue) ? w[m * Ktrue + k] : 0.0f;
    float hf = __uint_as_float(__float_as_uint(v) & 0xFFFF0000u);
    hi[idx] = (unsigned short)(__float_as_uint(v) >> 16);
    lo[idx] = (unsigned short)(__float_as_uint(v - hf) >> 16);
}

// ---------------- wmma split-bf16 conv (all conv layers) ----------------
// GEMM: M=Cout (BM/tile), N=spatial (128/tile), K chunks of 32.
// A (weights): dense bf16 hi/lo planes -> cp.async(8B) to smem.
// B (acts): packed split words, register LDG gather + prmt.
template<int BM>
__global__ __launch_bounds__(256, 2)
void conv_tc(const unsigned short* __restrict__ wh, const unsigned short* __restrict__ wl,
             const unsigned* __restrict__ inp, float* __restrict__ out,
             const float* __restrict__ bias, float scale,
             int Cin, int D, int H, int W, int Ktrue, int K, int Cout, int Ntotal)
{
    constexpr int ASZ  = BM * 80;         // bytes per A plane (stride 40 bf16)
    constexpr int BHI  = 2 * ASZ;
    constexpr int BLO  = BHI + 10240;
    constexpr int TCB  = BHI + 20480;     // bytes per buffer
    constexpr int AI   = BM / 32;
    extern __shared__ char dsm[];
    char* albase = (char*)(((uintptr_t)dsm + 1023) & ~(uintptr_t)1023);
    const uint32_t sbase = smem_u32(albase);

    const int Hp = H + 2, Wp = W + 2;
    const int HWp = Hp * Wp;
    const int chanStride = (D + 2) * HWp;
    const int HW = H * W;
    const int DHW = D * HW;

    const int t = threadIdx.x;
    const int wid = t >> 5;
    const int ntile = blockIdx.x;
    const int mtile = blockIdx.y;

    // ---- A: cp.async dense copy ----
    auto CPA = [&](int bufIdx, int k0) {
        uint32_t dst0 = sbase + bufIdx * TCB;
#pragma unroll
        for (int i = 0; i < BM / 16; ++i) {
            int c = t + 256 * i;
            int plane = c / (BM * 8);
            int rem = c - plane * (BM * 8);
            int row = rem >> 3, q = rem & 7;
            const unsigned short* src = (plane ? wl : wh) + (size_t)(mtile * BM + row) * K + k0 + q * 4;
            cp_async8(dst0 + plane * ASZ + row * 80 + q * 8, src);
        }
        asm volatile("cp.async.commit_group;");
    };

    // ---- B gather (coalesced along N): nl = lane->n, kb = warp->4 k ----
    const int nl = t & 31;
    const int kb = (t >> 5) << 2;
    int nbB[4];
#pragma unroll
    for (int i = 0; i < 4; ++i) {
        int n = ntile * 128 + i * 32 + nl;
        if (n >= Ntotal) n = Ntotal - 1;
        int b = n / DHW;
        int rem = n - b * DHW;
        int d = rem / HW;
        int r2 = rem - d * HW;
        int h = r2 / W;
        int w = r2 - h * W;
        nbB[i] = b * Cin * chanStride + d * HWp + h * Wp + w;
    }

    uint32_t bw[4][4];
    auto LOADB = [&](int k0) {
        int ko[4];
#pragma unroll
        for (int j = 0; j < 4; ++j) {
            int k = k0 + kb + j;
            if (k >= Ktrue) k = 0;   // padded K: weight is 0, any valid addr
            int ci = k / 27, r_ = k - ci * 27;
            int kd = r_ / 9; r_ -= kd * 9;
            int kh = r_ / 3, kw = r_ - kh * 3;
            ko[j] = ci * chanStride + kd * HWp + kh * Wp + kw;
        }
#pragma unroll
        for (int i = 0; i < 4; ++i)
#pragma unroll
            for (int j = 0; j < 4; ++j)
                bw[i][j] = __ldg(inp + nbB[i] + ko[j]);
    };
    auto STOREB = [&](char* sb) {
#pragma unroll
        for (int i = 0; i < 4; ++i)
#pragma unroll
            for (int jp = 0; jp < 2; ++jp) {
                int j = jp * 2;
                uint32_t bhi, blo;
                asm("prmt.b32 %0, %1, %2, 0x5410;" : "=r"(bhi) : "r"(bw[i][j]), "r"(bw[i][j + 1]));
                asm("prmt.b32 %0, %1, %2, 0x7632;" : "=r"(blo) : "r"(bw[i][j]), "r"(bw[i][j + 1]));
                int off = (i * 32 + nl) * 80 + (kb + j) * 2;
                *(uint32_t*)(sb + BHI + off) = bhi;
                *(uint32_t*)(sb + BLO + off) = blo;
            }
    };

    // ---- accumulators: warp (wm, wn) owns (BM/2) x 32 ----
    const int wm = wid >> 2;
    const int wn = wid & 3;
    wmma::fragment<wmma::accumulator, 16, 16, 16, float> acc[AI][2];
#pragma unroll
    for (int i = 0; i < AI; ++i)
#pragma unroll
        for (int j = 0; j < 2; ++j) wmma::fill_fragment(acc[i][j], 0.0f);

    auto COMPUTE = [&](char* sb) {
        const __nv_bfloat16* Ahi = (const __nv_bfloat16*)(sb);
        const __nv_bfloat16* Alo = (const __nv_bfloat16*)(sb + ASZ);
        const __nv_bfloat16* Bhi = (const __nv_bfloat16*)(sb + BHI);
        const __nv_bfloat16* Blo = (const __nv_bfloat16*)(sb + BLO);
#pragma unroll
        for (int ks = 0; ks < 2; ++ks) {
            wmma::fragment<wmma::matrix_b, 16, 16, 16, __nv_bfloat16, wmma::col_major> bh[2], bl[2];
#pragma unroll
            for (int j = 0; j < 2; ++j) {
                const int co = (wn * 32 + j * 16) * 40 + ks * 16;
                wmma::load_matrix_sync(bh[j], Bhi + co, 40);
                wmma::load_matrix_sync(bl[j], Blo + co, 40);
            }
#pragma unroll
            for (int i = 0; i < AI; ++i) {
                const int ro = (wm * (BM / 2) + i * 16) * 40 + ks * 16;
                wmma::fragment<wmma::matrix_a, 16, 16, 16, __nv_bfloat16, wmma::row_major> ah, al;
                wmma::load_matrix_sync(ah, Ahi + ro, 40);
                wmma::load_matrix_sync(al, Alo + ro, 40);
#pragma unroll
                for (int j = 0; j < 2; ++j) {
                    wmma::mma_sync(acc[i][j], ah, bh[j], acc[i][j]);
                    wmma::mma_sync(acc[i][j], ah, bl[j], acc[i][j]);
                    wmma::mma_sync(acc[i][j], al, bh[j], acc[i][j]);
                }
            }
        }
    };

    const int KT = K / 32;
    CPA(0, 0);
    LOADB(0);
    asm volatile("cp.async.wait_group 0;" ::: "memory");
    STOREB(albase);
    __syncthreads();
    for (int kc = 0; kc < KT; ++kc) {
        char* cur = albase + (kc & 1) * TCB;
        char* nxt = albase + ((kc & 1) ^ 1) * TCB;
        if (kc + 1 < KT) {
            CPA((kc & 1) ^ 1, (kc + 1) * 32);
            LOADB((kc + 1) * 32);
        }
        COMPUTE(cur);
        if (kc + 1 < KT) {
            asm volatile("cp.async.wait_group 0;" ::: "memory");
            STOREB(nxt);
        }
        __syncthreads();
    }

    // ---- epilogue: stage BMx128 fp32 in smem, coalesced scatter ----
    float* stage = (float*)albase;
#pragma unroll
    for (int i = 0; i < AI; ++i)
#pragma unroll
        for (int j = 0; j < 2; ++j)
            wmma::store_matrix_sync(stage + (wm * (BM / 2) + i * 16) * 132 + (wn * 32 + j * 16),
                                    acc[i][j], 132, wmma::mem_row_major);
    __syncthreads();
    {
        const int jn = t & 127, rh = t >> 7;
        const int n = ntile * 128 + jn;
        if (n < Ntotal) {
            int b = n / DHW, rem = n - b * DHW;
            size_t obase = ((size_t)b * Cout) * DHW + rem;
#pragma unroll 4
            for (int i = 0; i < BM / 2; ++i) {
                int m = rh * (BM / 2) + i;
                int mg = mtile * BM + m;
                float v = scale * (stage[m * 132 + jn] + bias[mg]);
                out[obase + (size_t)mg * DHW] = fmaxf(v, 0.0f);
            }
        }
    }
}

// ---------------- maxpool + pad (grid: x=HWp, y=Dp, z=plane) ----------------
__global__ void pool_pad_kernel(const float* __restrict__ in, float* __restrict__ out,
                                int D, int H, int W,
                                int kd, int kh, int kw, int sd, int sh, int sw,
                                int pd, int ph, int pw,
                                int Do, int Ho, int Wo, int cp, int split)
{
    const int plane = blockIdx.z;
    const int z = blockIdx.y;
    const int Hp = Ho + 2 * cp, Wp = Wo + 2 * cp, Dp = Do + 2 * cp;
    const int HWp = Hp * Wp;
    const int s = blockIdx.x * blockDim.x + threadIdx.x;
    if (s >= HWp) return;
    int y = s / Wp;
    int x = s - y * Wp;
    float v = 0.0f;
    int od = z - cp, oh = y - cp, ow = x - cp;
    if (od >= 0 && od < Do && oh >= 0 && oh < Ho && ow >= 0 && ow < Wo) {
        float m = -3.4e38f;
        int id0 = od * sd - pd, ih0 = oh * sh - ph, iw0 = ow * sw - pw;
        const float* base = in + (long)plane * D * H * W;
        for (int a = 0; a < kd; ++a) {
            int id = id0 + a;
            if (id < 0 || id >= D) continue;
            for (int e = 0; e < kh; ++e) {
                int ih = ih0 + e;
                if (ih < 0 || ih >= H) continue;
                for (int f = 0; f < kw; ++f) {
                    int iw = iw0 + f;
                    if (iw < 0 || iw >= W) continue;
                    float q = base[(id * H + ih) * W + iw];
                    m = fmaxf(m, q);
                }
            }
        }
        v = m;
    }
    long oi = ((long)plane * Dp + z) * HWp + s;
    if (split) ((unsigned*)out)[oi] = pack_split(v);
    else out[oi] = v;
}

// ---------------- tiled FC ----------------
__global__ __launch_bounds__(256)
void fc_tile_kernel(const float* __restrict__ x, const float* __restrict__ W,
                    const float* __restrict__ b, float* __restrict__ y,
                    int K, int M, float scale)
{
    __shared__ float xs[24][260];
    const int warp = threadIdx.x >> 5, lane = threadIdx.x & 31;
    const int m = blockIdx.x * 8 + warp;
    float acc[24];
#pragma unroll
    for (int n = 0; n < 24; ++n) acc[n] = 0.0f;

    const float* wr = W + (size_t)m * K;
    for (int k0 = 0; k0 < K; k0 += 256) {
        __syncthreads();
        for (int i = threadIdx.x; i < 24 * 64; i += 256) {
            int n = i / 64, kq = i - n * 64;
            *(float4*)&xs[n][kq * 4] = *(const float4*)(x + (size_t)n * K + k0 + kq * 4);
        }
        __syncthreads();
#pragma unroll 2
        for (int kq = lane; kq < 64; kq += 32) {
            float4 w4 = *(const float4*)(wr + k0 + kq * 4);
#pragma unroll
            for (int n = 0; n < 24; ++n) {
                float4 x4 = *(const float4*)&xs[n][kq * 4];
                acc[n] += w4.x * x4.x + w4.y * x4.y + w4.z * x4.z + w4.w * x4.w;
            }
        }
    }
#pragma unroll
    for (int n = 0; n < 24; ++n) {
#pragma unroll
        for (int o = 16; o > 0; o >>= 1)
            acc[n] += __shfl_xor_sync(0xFFFFFFFFu, acc[n], o);
    }
    if (lane == 0) {
#pragma unroll
        for (int n = 0; n < 24; ++n) {
            float v = scale * (acc[n] + b[m]);
            y[(size_t)n * M + m] = fmaxf(v, 0.0f);
        }
    }
}

__global__ void rownorm_kernel(const float* __restrict__ x, float* __restrict__ nrm, int K)
{
    int row = blockIdx.x;
    float s = 0.0f;
    for (int k = threadIdx.x; k < K; k += 128) {
        float v = x[(size_t)row * K + k];
        s += v * v;
    }
    __shared__ float sm[128];
    sm[threadIdx.x] = s;
    __syncthreads();
    for (int o = 64; o > 0; o >>= 1) {
        if (threadIdx.x < o) sm[threadIdx.x] += sm[threadIdx.x + o];
        __syncthreads();
    }
    if (threadIdx.x == 0) nrm[row] = sqrtf(sm[0]);
}

__global__ void cost_kernel(const float* __restrict__ feat, const float* __restrict__ nrm,
                            float* __restrict__ cost)
{
    int bi = blockIdx.x;
    int j = bi & 3, t2 = bi >> 2;
    int i = t2 & 3, t3 = t2 >> 2;
    int s = t3 % 3, q = t3 / 3;
    int qrow = 12 + q * 4 + i;
    int srow = s * 4 + j;
    const float* a = feat + (size_t)qrow * 4096;
    const float* c = feat + (size_t)srow * 4096;
    float pr = 0.0f;
    for (int k = threadIdx.x; k < 4096; k += 128) pr += a[k] * c[k];
    __shared__ float sm[128];
    sm[threadIdx.x] = pr;
    __syncthreads();
    for (int o = 64; o > 0; o >>= 1) {
        if (threadIdx.x < o) sm[threadIdx.x] += sm[threadIdx.x + o];
        __syncthreads();
    }
    if (threadIdx.x == 0)
        cost[bi] = 1.0f - sm[0] / ((nrm[qrow] + 1e-8f) * (nrm[srow] + 1e-8f));
}

__global__ void sinkhorn_kernel(const float* __restrict__ cost, float* __restrict__ outp)
{
    int t = threadIdx.x;
    if (t >= 9) return;
    float sem[16], Km[16];
    for (int i = 0; i < 4; ++i)
        for (int j = 0; j < 4; ++j) {
            float sc = cost[t * 16 + i * 4 + j];
            float ti = i * 0.25f, tj = j * 0.25f;
            float d2 = (ti - tj) * (ti - tj);
            float pos = expf(-1.0f / (d2 + 1.0f));
            sem[i * 4 + j] = sc;
            Km[i * 4 + j] = expf(-7.0f * (sc + 0.4f * pos));
        }
    float u[4] = {0.25f, 0.25f, 0.25f, 0.25f}, v[4];
    for (int it = 0; it < 100; ++it) {
        for (int j = 0; j < 4; ++j) {
            float s = 1e-9f;
            for (int i = 0; i < 4; ++i) s += Km[i * 4 + j] * u[i];
            v[j] = 0.25f / s;
        }
        for (int i = 0; i < 4; ++i) {
            float s = 1e-9f;
            for (int j = 0; j < 4; ++j) s += Km[i * 4 + j] * v[j];
            u[i] = 0.25f / s;
        }
    }
    for (int j = 0; j < 4; ++j) {
        float s = 1e-9f;
        for (int i = 0; i < 4; ++i) s += Km[i * 4 + j] * u[i];
        v[j] = 0.25f / s;
    }
    float tr = 0.0f;
    for (int i = 0; i < 4; ++i)
        for (int j = 0; j < 4; ++j)
            tr += u[i] * Km[i * 4 + j] * v[j] * sem[i * 4 + j];
    outp[t] = -tr;
}

// ---------------- driver ----------------
static inline int cdiv_i(long a, long b) { return (int)((a + b - 1) / b); }

extern "C" void kernel_launch(void* const* d_in, const int* in_sizes, int n_in,
                              void* d_out, int out_size)
{
    const float* sup  = (const float*)d_in[0];
    const float* qry  = (const float*)d_in[1];
    const float* w1   = (const float*)d_in[2];
    const float* b1   = (const float*)d_in[3];
    const float* w2   = (const float*)d_in[4];
    const float* b2   = (const float*)d_in[5];
    const float* w3a  = (const float*)d_in[6];
    const float* b3a  = (const float*)d_in[7];
    const float* w3b  = (const float*)d_in[8];
    const float* b3b  = (const float*)d_in[9];
    const float* w4a  = (const float*)d_in[10];
    const float* b4a  = (const float*)d_in[11];
    const float* w4b  = (const float*)d_in[12];
    const float* b4b  = (const float*)d_in[13];
    const float* w5a  = (const float*)d_in[14];
    const float* b5a  = (const float*)d_in[15];
    const float* w5b  = (const float*)d_in[16];
    const float* b5b  = (const float*)d_in[17];
    const float* fw6  = (const float*)d_in[18];
    const float* fb6  = (const float*)d_in[19];
    const float* fw7  = (const float*)d_in[20];
    const float* fb7  = (const float*)d_in[21];

    float *pad, *act, *feat, *fc6o, *fc7o, *nrm, *cst;
    unsigned short *wh, *wl;
    cudaGetSymbolAddress((void**)&pad,  g_pad);
    cudaGetSymbolAddress((void**)&act,  g_act);
    cudaGetSymbolAddress((void**)&feat, g_feat);
    cudaGetSymbolAddress((void**)&fc6o, g_fc6);
    cudaGetSymbolAddress((void**)&fc7o, g_fc7);
    cudaGetSymbolAddress((void**)&nrm,  g_norm);
    cudaGetSymbolAddress((void**)&cst,  g_cost);
    cudaGetSymbolAddress((void**)&wh,   g_wh);
    cudaGetSymbolAddress((void**)&wl,   g_wl);

    const float SC = BN_SCALE_F;
    const int TC_SMEM128 = 2 * (2 * 128 * 80 + 20480) + 1024;  // 82944
    const int TC_SMEM64  = 2 * (2 * 64 * 80 + 20480) + 1024;   // 62464
    cudaFuncSetAttribute(conv_tc<128>, cudaFuncAttributeMaxDynamicSharedMemorySize, TC_SMEM128);
    cudaFuncSetAttribute(conv_tc<64>,  cudaFuncAttributeMaxDynamicSharedMemorySize, TC_SMEM64);

    // weight plane offsets (elements)
    const long O2 = 0, O3A = 221184, O3B = 1105920, O4A = 2875392;
    const long O4B = 6414336, O5A = 13492224, O5B = 20570112, O1 = 27648000;

    // launch order: 6th launch (ncu -s 5 -c 1) = conv2's conv_tc<128>
    rearrange_pad_kernel<<<dim3(cdiv_i(114 * 114, 256), 18, 72), 256>>>(sup, qry, (unsigned*)pad);  // 1
    wsplit_kernel<<<cdiv_i(6144, 256), 256>>>(w1, wh + O1, wl + O1, 81, 96, 6144);                  // 2
    conv_tc<64><<<dim3(37632, 1), 256, TC_SMEM64>>>(wh + O1, wl + O1, (unsigned*)pad, act, b1, SC,  // 3
                                                    3, 16, 112, 112, 81, 96, 64, 4816896);
    pool_pad_kernel<<<dim3(cdiv_i(58 * 58, 256), 18, 24 * 64), 256>>>(                              // 4
        act, pad, 16, 112, 112, 1, 2, 2, 1, 2, 2, 0, 0, 0, 16, 56, 56, 1, 1);
    wsplit_kernel<<<cdiv_i(221184, 256), 256>>>(w2, wh + O2, wl + O2, 1728, 1728, 221184);          // 5
    conv_tc<128><<<dim3(9408, 1), 256, TC_SMEM128>>>(wh + O2, wl + O2, (unsigned*)pad, act, b2, SC, // 6 <- ncu
                                                     64, 16, 56, 56, 1728, 1728, 128, 1204224);
    pool_pad_kernel<<<dim3(cdiv_i(30 * 30, 256), 10, 24 * 128), 256>>>(
        act, pad, 16, 56, 56, 2, 2, 2, 2, 2, 2, 0, 0, 0, 8, 28, 28, 1, 1);
    wsplit_kernel<<<cdiv_i(884736, 256), 256>>>(w3a, wh + O3A, wl + O3A, 3456, 3456, 884736);
    conv_tc<128><<<dim3(1176, 2), 256, TC_SMEM128>>>(wh + O3A, wl + O3A, (unsigned*)pad, act, b3a, 1.0f,
                                                     128, 8, 28, 28, 3456, 3456, 256, 150528);
    pool_pad_kernel<<<dim3(cdiv_i(30 * 30, 256), 10, 24 * 256), 256>>>(
        act, pad, 8, 28, 28, 1, 1, 1, 1, 1, 1, 0, 0, 0, 8, 28, 28, 1, 1);
    wsplit_kernel<<<cdiv_i(1769472, 256), 256>>>(w3b, wh + O3B, wl + O3B, 6912, 6912, 1769472);
    conv_tc<128><<<dim3(1176, 2), 256, TC_SMEM128>>>(wh + O3B, wl + O3B, (unsigned*)pad, act, b3b, SC,
                                                     256, 8, 28, 28, 6912, 6912, 256, 150528);
    pool_pad_kernel<<<dim3(1, 6, 24 * 256), 256>>>(
        act, pad, 8, 28, 28, 2, 2, 2, 2, 2, 2, 0, 0, 0, 4, 14, 14, 1, 1);
    wsplit_kernel<<<cdiv_i(3538944, 256), 256>>>(w4a, wh + O4A, wl + O4A, 6912, 6912, 3538944);
    conv_tc<128><<<dim3(147, 4), 256, TC_SMEM128>>>(wh + O4A, wl + O4A, (unsigned*)pad, act, b4a, 1.0f,
                                                    256, 4, 14, 14, 6912, 6912, 512, 18816);
    pool_pad_kernel<<<dim3(1, 6, 24 * 512), 256>>>(
        act, pad, 4, 14, 14, 1, 1, 1, 1, 1, 1, 0, 0, 0, 4, 14, 14, 1, 1);
    wsplit_kernel<<<cdiv_i(7077888, 256), 256>>>(w4b, wh + O4B, wl + O4B, 13824, 13824, 7077888);
    conv_tc<128><<<dim3(147, 4), 256, TC_SMEM128>>>(wh + O4B, wl + O4B, (unsigned*)pad, act, b4b, SC,
                                                    512, 4, 14, 14, 13824, 13824, 512, 18816);
    pool_pad_kernel<<<dim3(1, 4, 24 * 512), 256>>>(
        act, pad, 4, 14, 14, 2, 2, 2, 2, 2, 2, 0, 0, 0, 2, 7, 7, 1, 1);
    wsplit_kernel<<<cdiv_i(7077888, 256), 256>>>(w5a, wh + O5A, wl + O5A, 13824, 13824, 7077888);
    // conv5a/b: BM=64 -> 19x8 = 152 blocks (full wave)
    conv_tc<64><<<dim3(19, 8), 256, TC_SMEM64>>>(wh + O5A, wl + O5A, (unsigned*)pad, act, b5a, 1.0f,
                                                 512, 2, 7, 7, 13824, 13824, 512, 2352);
    pool_pad_kernel<<<dim3(1, 4, 24 * 512), 256>>>(
        act, pad, 2, 7, 7, 1, 1, 1, 1, 1, 1, 0, 0, 0, 2, 7, 7, 1, 1);
    wsplit_kernel<<<cdiv_i(7077888, 256), 256>>>(w5b, wh + O5B, wl + O5B, 13824, 13824, 7077888);
    conv_tc<64><<<dim3(19, 8), 256, TC_SMEM64>>>(wh + O5B, wl + O5B, (unsigned*)pad, act, b5b, SC,
                                                 512, 2, 7, 7, 13824, 13824, 512, 2352);
    // pool5 -> features (fp32)
    pool_pad_kernel<<<dim3(1, 1, 24 * 512), 256>>>(
        act, feat, 2, 7, 7, 2, 2, 2, 2, 2, 2, 0, 1, 1, 1, 4, 4, 0, 0);
    // fc6, fc7
    fc_tile_kernel<<<512, 256>>>(feat, fw6, fb6, fc6o, 8192, 4096, SC);
    fc_tile_kernel<<<512, 256>>>(fc6o, fw7, fb7, fc7o, 4096, 4096, SC);
    // head
    rownorm_kernel<<<24, 128>>>(fc7o, nrm, 4096);
    cost_kernel<<<144, 128>>>(fc7o, nrm, cst);
    sinkhorn_kernel<<<1, 32>>>(cst, (float*)d_out);
}

// round 16
// speedup vs baseline: 1.2177x; 1.0364x over previous
#include <cuda_runtime.h>
#include <cuda_bf16.h>
#include <mma.h>
#include <math.h>
#include <stdint.h>

using namespace nvcuda;

#define BN_SCALE_F 0.9999950000374996f

// ---------------- static scratch ----------------
__device__ float g_pad[93007872];
__device__ float g_act[308281344];
__device__ float g_feat[24 * 8192];
__device__ float g_fc6[24 * 4096];
__device__ float g_fc7[24 * 4096];
__device__ float g_norm[24];
__device__ float g_cost[144];
__device__ unsigned short g_wh[27654144];  // bf16 hi planes: conv2..conv5b, then conv1(Kpad 96)
__device__ unsigned short g_wl[27654144];  // bf16 lo planes

// ---------------- helpers ----------------
__device__ __forceinline__ unsigned pack_split(float v) {
    float hf = __uint_as_float(__float_as_uint(v) & 0xFFFF0000u);
    unsigned hi = __float_as_uint(hf) >> 16;
    float r = v - hf;
    unsigned lo = __float_as_uint(r) >> 16;
    return hi | (lo << 16);
}
__device__ __forceinline__ uint32_t smem_u32(const void* p) {
    uint32_t a;
    asm("{ .reg .u64 t; cvta.to.shared.u64 t, %1; cvt.u32.u64 %0, t; }" : "=r"(a) : "l"(p));
    return a;
}
__device__ __forceinline__ void cp_async8(uint32_t dst, const void* src) {
    asm volatile("cp.async.ca.shared.global [%0], [%1], 8;" :: "r"(dst), "l"(src));
}

// ---------------- zero fill ----------------
__global__ void zero_kernel(unsigned* __restrict__ p, int n)
{
    int i = blockIdx.x * blockDim.x + threadIdx.x;
    if (i < n) p[i] = 0u;
}

// ---------------- input rearrange + pad -> packed split words ----------------
__global__ void rearrange_pad_kernel(const float* __restrict__ sup, const float* __restrict__ qry,
                                     unsigned* __restrict__ out)
{
    const int plane = blockIdx.z;          // clip*3 + c
    const int dz = blockIdx.y;             // 0..17
    const int clip = plane / 3;
    const int c = plane - clip * 3;
    const int s = blockIdx.x * blockDim.x + threadIdx.x;
    const int HWp = 114 * 114;
    if (s >= HWp) return;
    int hy = s / 114;
    int wx = s - hy * 114;
    float val = 0.0f;
    if (dz >= 1 && dz <= 16 && hy >= 1 && hy <= 112 && wx >= 1 && wx <= 112) {
        int tt = dz - 1, h = hy - 1, w = wx - 1;
        const float* src = (clip < 12) ? sup : qry;
        int cc = (clip < 12) ? clip : clip - 12;
        long addr = ((((long)cc * 16 + tt) * 3 + c) * 112 + h) * 112 + w;
        val = src[addr];
    }
    out[((long)plane * 18 + dz) * HWp + s] = pack_split(val);
}

// split weights fp32 -> separate bf16 hi/lo planes, optional K padding
__global__ void wsplit_kernel(const float* __restrict__ w, unsigned short* __restrict__ hi,
                              unsigned short* __restrict__ lo, int Ktrue, int Kpad, int total)
{
    int idx = blockIdx.x * blockDim.x + threadIdx.x;
    if (idx >= total) return;
    int m = idx / Kpad, k = idx - m * Kpad;
    float v = (k < Ktrue) ? w[m * Ktrue + k] : 0.0f;
    float hf = __uint_as_float(__float_as_uint(v) & 0xFFFF0000u);
    hi[idx] = (unsigned short)(__float_as_uint(v) >> 16);
    lo[idx] = (unsigned short)(__float_as_uint(v - hf) >> 16);
}

// ---------------- wmma split-bf16 conv (all conv layers) ----------------
// GEMM: M=Cout (BM/tile), N=spatial (128/tile), K chunks of 32.
// A (weights): dense bf16 hi/lo planes -> cp.async(8B).  B: register LDG + prmt.
// padout=1: write pack_split(relu) into padded split layout [b*Cout+m][D+2][H+2][W+2].
template<int BM>
__global__ __launch_bounds__(256, 2)
void conv_tc(const unsigned short* __restrict__ wh, const unsigned short* __restrict__ wl,
             const unsigned* __restrict__ inp, float* __restrict__ out,
             const float* __restrict__ bias, float scale,
             int Cin, int D, int H, int W, int Ktrue, int K, int Cout, int Ntotal, int padout)
{
    constexpr int ASZ  = BM * 80;
    constexpr int BHI  = 2 * ASZ;
    constexpr int BLO  = BHI + 10240;
    constexpr int TCB  = BHI + 20480;
    constexpr int AI   = BM / 32;
    extern __shared__ char dsm[];
    char* albase = (char*)(((uintptr_t)dsm + 1023) & ~(uintptr_t)1023);
    const uint32_t sbase = smem_u32(albase);

    const int Hp = H + 2, Wp = W + 2;
    const int HWp = Hp * Wp;
    const int chanStride = (D + 2) * HWp;
    const int HW = H * W;
    const int DHW = D * HW;

    const int t = threadIdx.x;
    const int wid = t >> 5;
    const int ntile = blockIdx.x;
    const int mtile = blockIdx.y;

    auto CPA = [&](int bufIdx, int k0) {
        uint32_t dst0 = sbase + bufIdx * TCB;
#pragma unroll
        for (int i = 0; i < BM / 16; ++i) {
            int c = t + 256 * i;
            int plane = c / (BM * 8);
            int rem = c - plane * (BM * 8);
            int row = rem >> 3, q = rem & 7;
            const unsigned short* src = (plane ? wl : wh) + (size_t)(mtile * BM + row) * K + k0 + q * 4;
            cp_async8(dst0 + plane * ASZ + row * 80 + q * 8, src);
        }
        asm volatile("cp.async.commit_group;");
    };

    const int nl = t & 31;
    const int kb = (t >> 5) << 2;
    int nbB[4];
#pragma unroll
    for (int i = 0; i < 4; ++i) {
        int n = ntile * 128 + i * 32 + nl;
        if (n >= Ntotal) n = Ntotal - 1;
        int b = n / DHW;
        int rem = n - b * DHW;
        int d = rem / HW;
        int r2 = rem - d * HW;
        int h = r2 / W;
        int w = r2 - h * W;
        nbB[i] = b * Cin * chanStride + d * HWp + h * Wp + w;
    }

    uint32_t bw[4][4];
    auto LOADB = [&](int k0) {
        int ko[4];
#pragma unroll
        for (int j = 0; j < 4; ++j) {
            int k = k0 + kb + j;
            if (k >= Ktrue) k = 0;
            int ci = k / 27, r_ = k - ci * 27;
            int kd = r_ / 9; r_ -= kd * 9;
            int kh = r_ / 3, kw = r_ - kh * 3;
            ko[j] = ci * chanStride + kd * HWp + kh * Wp + kw;
        }
#pragma unroll
        for (int i = 0; i < 4; ++i)
#pragma unroll
            for (int j = 0; j < 4; ++j)
                bw[i][j] = __ldg(inp + nbB[i] + ko[j]);
    };
    auto STOREB = [&](char* sb) {
#pragma unroll
        for (int i = 0; i < 4; ++i)
#pragma unroll
            for (int jp = 0; jp < 2; ++jp) {
                int j = jp * 2;
                uint32_t bhi, blo;
                asm("prmt.b32 %0, %1, %2, 0x5410;" : "=r"(bhi) : "r"(bw[i][j]), "r"(bw[i][j + 1]));
                asm("prmt.b32 %0, %1, %2, 0x7632;" : "=r"(blo) : "r"(bw[i][j]), "r"(bw[i][j + 1]));
                int off = (i * 32 + nl) * 80 + (kb + j) * 2;
                *(uint32_t*)(sb + BHI + off) = bhi;
                *(uint32_t*)(sb + BLO + off) = blo;
            }
    };

    const int wm = wid >> 2;
    const int wn = wid & 3;
    wmma::fragment<wmma::accumulator, 16, 16, 16, float> acc[AI][2];
#pragma unroll
    for (int i = 0; i < AI; ++i)
#pragma unroll
        for (int j = 0; j < 2; ++j) wmma::fill_fragment(acc[i][j], 0.0f);

    auto COMPUTE = [&](char* sb) {
        const __nv_bfloat16* Ahi = (const __nv_bfloat16*)(sb);
        const __nv_bfloat16* Alo = (const __nv_bfloat16*)(sb + ASZ);
        const __nv_bfloat16* Bhi = (const __nv_bfloat16*)(sb + BHI);
        const __nv_bfloat16* Blo = (const __nv_bfloat16*)(sb + BLO);
#pragma unroll
        for (int ks = 0; ks < 2; ++ks) {
            wmma::fragment<wmma::matrix_b, 16, 16, 16, __nv_bfloat16, wmma::col_major> bh[2], bl[2];
#pragma unroll
            for (int j = 0; j < 2; ++j) {
                const int co = (wn * 32 + j * 16) * 40 + ks * 16;
                wmma::load_matrix_sync(bh[j], Bhi + co, 40);
                wmma::load_matrix_sync(bl[j], Blo + co, 40);
            }
#pragma unroll
            for (int i = 0; i < AI; ++i) {
                const int ro = (wm * (BM / 2) + i * 16) * 40 + ks * 16;
                wmma::fragment<wmma::matrix_a, 16, 16, 16, __nv_bfloat16, wmma::row_major> ah, al;
                wmma::load_matrix_sync(ah, Ahi + ro, 40);
                wmma::load_matrix_sync(al, Alo + ro, 40);
#pragma unroll
                for (int j = 0; j < 2; ++j) {
                    wmma::mma_sync(acc[i][j], ah, bh[j], acc[i][j]);
                    wmma::mma_sync(acc[i][j], ah, bl[j], acc[i][j]);
                    wmma::mma_sync(acc[i][j], al, bh[j], acc[i][j]);
                }
            }
        }
    };

    const int KT = K / 32;
    CPA(0, 0);
    LOADB(0);
    asm volatile("cp.async.wait_group 0;" ::: "memory");
    STOREB(albase);
    __syncthreads();
    for (int kc = 0; kc < KT; ++kc) {
        char* cur = albase + (kc & 1) * TCB;
        char* nxt = albase + ((kc & 1) ^ 1) * TCB;
        if (kc + 1 < KT) {
            CPA((kc & 1) ^ 1, (kc + 1) * 32);
            LOADB((kc + 1) * 32);
        }
        COMPUTE(cur);
        if (kc + 1 < KT) {
            asm volatile("cp.async.wait_group 0;" ::: "memory");
            STOREB(nxt);
        }
        __syncthreads();
    }

    // ---- epilogue ----
    float* stage = (float*)albase;
#pragma unroll
    for (int i = 0; i < AI; ++i)
#pragma unroll
        for (int j = 0; j < 2; ++j)
            wmma::store_matrix_sync(stage + (wm * (BM / 2) + i * 16) * 132 + (wn * 32 + j * 16),
                                    acc[i][j], 132, wmma::mem_row_major);
    __syncthreads();
    {
        const int jn = t & 127, rh = t >> 7;
        const int n = ntile * 128 + jn;
        if (n < Ntotal) {
            int b = n / DHW, rem = n - b * DHW;
            if (!padout) {
                size_t obase = ((size_t)b * Cout) * DHW + rem;
#pragma unroll 4
                for (int i = 0; i < BM / 2; ++i) {
                    int m = rh * (BM / 2) + i;
                    int mg = mtile * BM + m;
                    float v = scale * (stage[m * 132 + jn] + bias[mg]);
                    out[obase + (size_t)mg * DHW] = fmaxf(v, 0.0f);
                }
            } else {
                int d = rem / HW;
                int r2 = rem - d * HW;
                int h = r2 / W;
                int w = r2 - h * W;
                const long PD = (long)(D + 2) * HWp;
                long pbase = ((long)(d + 1) * Hp + (h + 1)) * Wp + (w + 1);
                unsigned* uo = (unsigned*)out;
                long base = (long)b * Cout * PD + pbase;
#pragma unroll 4
                for (int i = 0; i < BM / 2; ++i) {
                    int m = rh * (BM / 2) + i;
                    int mg = mtile * BM + m;
                    float v = scale * (stage[m * 132 + jn] + bias[mg]);
                    uo[base + (long)mg * PD] = pack_split(fmaxf(v, 0.0f));
                }
            }
        }
    }
}

// ---------------- specialized maxpool (stride=kernel, no in-pad) + conv-pad + split ----------------
template<int KD, int KH, int KW>
__global__ void pool_fast_kernel(const float* __restrict__ in, unsigned* __restrict__ out,
                                 int D, int H, int W, int Do, int Ho, int Wo)
{
    const int plane = blockIdx.z;
    const int z = blockIdx.y;              // 0..Do+1
    const int Hp = Ho + 2, Wp = Wo + 2;
    const int HWp = Hp * Wp;
    const int s = blockIdx.x * blockDim.x + threadIdx.x;
    if (s >= HWp) return;
    int y = s / Wp;
    int x = s - y * Wp;
    float v = 0.0f;
    int od = z - 1, oh = y - 1, ow = x - 1;
    if (od >= 0 && od < Do && oh >= 0 && oh < Ho && ow >= 0 && ow < Wo) {
        const float* base = in + (long)plane * D * H * W
                          + ((long)(od * KD) * H + oh * KH) * W + ow * KW;
        float m = -3.4e38f;
#pragma unroll
        for (int a = 0; a < KD; ++a)
#pragma unroll
            for (int e = 0; e < KH; ++e)
#pragma unroll
                for (int f = 0; f < KW; ++f)
                    m = fmaxf(m, base[(a * H + e) * W + f]);
        v = m;
    }
    out[((long)plane * (Do + 2) + z) * HWp + s] = pack_split(v);
}

// generic pool (pool5 only)
__global__ void pool_pad_kernel(const float* __restrict__ in, float* __restrict__ out,
                                int D, int H, int W,
                                int kd, int kh, int kw, int sd, int sh, int sw,
                                int pd, int ph, int pw,
                                int Do, int Ho, int Wo, int cp, int split)
{
    const int plane = blockIdx.z;
    const int z = blockIdx.y;
    const int Hp = Ho + 2 * cp, Wp = Wo + 2 * cp, Dp = Do + 2 * cp;
    const int HWp = Hp * Wp;
    const int s = blockIdx.x * blockDim.x + threadIdx.x;
    if (s >= HWp) return;
    int y = s / Wp;
    int x = s - y * Wp;
    float v = 0.0f;
    int od = z - cp, oh = y - cp, ow = x - cp;
    if (od >= 0 && od < Do && oh >= 0 && oh < Ho && ow >= 0 && ow < Wo) {
        float m = -3.4e38f;
        int id0 = od * sd - pd, ih0 = oh * sh - ph, iw0 = ow * sw - pw;
        const float* base = in + (long)plane * D * H * W;
        for (int a = 0; a < kd; ++a) {
            int id = id0 + a;
            if (id < 0 || id >= D) continue;
            for (int e = 0; e < kh; ++e) {
                int ih = ih0 + e;
                if (ih < 0 || ih >= H) continue;
                for (int f = 0; f < kw; ++f) {
                    int iw = iw0 + f;
                    if (iw < 0 || iw >= W) continue;
                    float q = base[(id * H + ih) * W + iw];
                    m = fmaxf(m, q);
                }
            }
        }
        v = m;
    }
    long oi = ((long)plane * Dp + z) * HWp + s;
    if (split) ((unsigned*)out)[oi] = pack_split(v);
    else out[oi] = v;
}

// ---------------- tiled FC ----------------
__global__ __launch_bounds__(256)
void fc_tile_kernel(const float* __restrict__ x, const float* __restrict__ W,
                    const float* __restrict__ b, float* __restrict__ y,
                    int K, int M, float scale)
{
    __shared__ float xs[24][260];
    const int warp = threadIdx.x >> 5, lane = threadIdx.x & 31;
    const int m = blockIdx.x * 8 + warp;
    float acc[24];
#pragma unroll
    for (int n = 0; n < 24; ++n) acc[n] = 0.0f;

    const float* wr = W + (size_t)m * K;
    for (int k0 = 0; k0 < K; k0 += 256) {
        __syncthreads();
        for (int i = threadIdx.x; i < 24 * 64; i += 256) {
            int n = i / 64, kq = i - n * 64;
            *(float4*)&xs[n][kq * 4] = *(const float4*)(x + (size_t)n * K + k0 + kq * 4);
        }
        __syncthreads();
#pragma unroll 2
        for (int kq = lane; kq < 64; kq += 32) {
            float4 w4 = *(const float4*)(wr + k0 + kq * 4);
#pragma unroll
            for (int n = 0; n < 24; ++n) {
                float4 x4 = *(const float4*)&xs[n][kq * 4];
                acc[n] += w4.x * x4.x + w4.y * x4.y + w4.z * x4.z + w4.w * x4.w;
            }
        }
    }
#pragma unroll
    for (int n = 0; n < 24; ++n) {
#pragma unroll
        for (int o = 16; o > 0; o >>= 1)
            acc[n] += __shfl_xor_sync(0xFFFFFFFFu, acc[n], o);
    }
    if (lane == 0) {
#pragma unroll
        for (int n = 0; n < 24; ++n) {
            float v = scale * (acc[n] + b[m]);
            y[(size_t)n * M + m] = fmaxf(v, 0.0f);
        }
    }
}

__global__ void rownorm_kernel(const float* __restrict__ x, float* __restrict__ nrm, int K)
{
    int row = blockIdx.x;
    float s = 0.0f;
    for (int k = threadIdx.x; k < K; k += 128) {
        float v = x[(size_t)row * K + k];
        s += v * v;
    }
    __shared__ float sm[128];
    sm[threadIdx.x] = s;
    __syncthreads();
    for (int o = 64; o > 0; o >>= 1) {
        if (threadIdx.x < o) sm[threadIdx.x] += sm[threadIdx.x + o];
        __syncthreads();
    }
    if (threadIdx.x == 0) nrm[row] = sqrtf(sm[0]);
}

__global__ void cost_kernel(const float* __restrict__ feat, const float* __restrict__ nrm,
                            float* __restrict__ cost)
{
    int bi = blockIdx.x;
    int j = bi & 3, t2 = bi >> 2;
    int i = t2 & 3, t3 = t2 >> 2;
    int s = t3 % 3, q = t3 / 3;
    int qrow = 12 + q * 4 + i;
    int srow = s * 4 + j;
    const float* a = feat + (size_t)qrow * 4096;
    const float* c = feat + (size_t)srow * 4096;
    float pr = 0.0f;
    for (int k = threadIdx.x; k < 4096; k += 128) pr += a[k] * c[k];
    __shared__ float sm[128];
    sm[threadIdx.x] = pr;
    __syncthreads();
    for (int o = 64; o > 0; o >>= 1) {
        if (threadIdx.x < o) sm[threadIdx.x] += sm[threadIdx.x + o];
        __syncthreads();
    }
    if (threadIdx.x == 0)
        cost[bi] = 1.0f - sm[0] / ((nrm[qrow] + 1e-8f) * (nrm[srow] + 1e-8f));
}

__global__ void sinkhorn_kernel(const float* __restrict__ cost, float* __restrict__ outp)
{
    int t = threadIdx.x;
    if (t >= 9) return;
    float sem[16], Km[16];
    for (int i = 0; i < 4; ++i)
        for (int j = 0; j < 4; ++j) {
            float sc = cost[t * 16 + i * 4 + j];
            float ti = i * 0.25f, tj = j * 0.25f;
            float d2 = (ti - tj) * (ti - tj);
            float pos = expf(-1.0f / (d2 + 1.0f));
            sem[i * 4 + j] = sc;
            Km[i * 4 + j] = expf(-7.0f * (sc + 0.4f * pos));
        }
    float u[4] = {0.25f, 0.25f, 0.25f, 0.25f}, v[4];
    for (int it = 0; it < 100; ++it) {
        for (int j = 0; j < 4; ++j) {
            float s = 1e-9f;
            for (int i = 0; i < 4; ++i) s += Km[i * 4 + j] * u[i];
            v[j] = 0.25f / s;
        }
        for (int i = 0; i < 4; ++i) {
            float s = 1e-9f;
            for (int j = 0; j < 4; ++j) s += Km[i * 4 + j] * v[j];
            u[i] = 0.25f / s;
        }
    }
    for (int j = 0; j < 4; ++j) {
        float s = 1e-9f;
        for (int i = 0; i < 4; ++i) s += Km[i * 4 + j] * u[i];
        v[j] = 0.25f / s;
    }
    float tr = 0.0f;
    for (int i = 0; i < 4; ++i)
        for (int j = 0; j < 4; ++j)
            tr += u[i] * Km[i * 4 + j] * v[j] * sem[i * 4 + j];
    outp[t] = -tr;
}

// ---------------- driver ----------------
static inline int cdiv_i(long a, long b) { return (int)((a + b - 1) / b); }

extern "C" void kernel_launch(void* const* d_in, const int* in_sizes, int n_in,
                              void* d_out, int out_size)
{
    const float* sup  = (const float*)d_in[0];
    const float* qry  = (const float*)d_in[1];
    const float* w1   = (const float*)d_in[2];
    const float* b1   = (const float*)d_in[3];
    const float* w2   = (const float*)d_in[4];
    const float* b2   = (const float*)d_in[5];
    const float* w3a  = (const float*)d_in[6];
    const float* b3a  = (const float*)d_in[7];
    const float* w3b  = (const float*)d_in[8];
    const float* b3b  = (const float*)d_in[9];
    const float* w4a  = (const float*)d_in[10];
    const float* b4a  = (const float*)d_in[11];
    const float* w4b  = (const float*)d_in[12];
    const float* b4b  = (const float*)d_in[13];
    const float* w5a  = (const float*)d_in[14];
    const float* b5a  = (const float*)d_in[15];
    const float* w5b  = (const float*)d_in[16];
    const float* b5b  = (const float*)d_in[17];
    const float* fw6  = (const float*)d_in[18];
    const float* fb6  = (const float*)d_in[19];
    const float* fw7  = (const float*)d_in[20];
    const float* fb7  = (const float*)d_in[21];

    float *pad, *act, *feat, *fc6o, *fc7o, *nrm, *cst;
    unsigned short *wh, *wl;
    cudaGetSymbolAddress((void**)&pad,  g_pad);
    cudaGetSymbolAddress((void**)&act,  g_act);
    cudaGetSymbolAddress((void**)&feat, g_feat);
    cudaGetSymbolAddress((void**)&fc6o, g_fc6);
    cudaGetSymbolAddress((void**)&fc7o, g_fc7);
    cudaGetSymbolAddress((void**)&nrm,  g_norm);
    cudaGetSymbolAddress((void**)&cst,  g_cost);
    cudaGetSymbolAddress((void**)&wh,   g_wh);
    cudaGetSymbolAddress((void**)&wl,   g_wl);

    const float SC = BN_SCALE_F;
    const int TC_SMEM128 = 2 * (2 * 128 * 80 + 20480) + 1024;
    const int TC_SMEM64  = 2 * (2 * 64 * 80 + 20480) + 1024;
    cudaFuncSetAttribute(conv_tc<128>, cudaFuncAttributeMaxDynamicSharedMemorySize, TC_SMEM128);
    cudaFuncSetAttribute(conv_tc<64>,  cudaFuncAttributeMaxDynamicSharedMemorySize, TC_SMEM64);

    const long O2 = 0, O3A = 221184, O3B = 1105920, O4A = 2875392;
    const long O4B = 6414336, O5A = 13492224, O5B = 20570112, O1 = 27648000;

    // launch order: 6th launch (ncu -s 5 -c 1) = conv2's conv_tc<128>
    rearrange_pad_kernel<<<dim3(cdiv_i(114 * 114, 256), 18, 72), 256>>>(sup, qry, (unsigned*)pad);  // 1
    wsplit_kernel<<<cdiv_i(6144, 256), 256>>>(w1, wh + O1, wl + O1, 81, 96, 6144);                  // 2
    conv_tc<64><<<dim3(37632, 1), 256, TC_SMEM64>>>(wh + O1, wl + O1, (unsigned*)pad, act, b1, SC,  // 3
                                                    3, 16, 112, 112, 81, 96, 64, 4816896, 0);
    pool_fast_kernel<1, 2, 2><<<dim3(cdiv_i(58 * 58, 256), 18, 24 * 64), 256>>>(                    // 4
        act, (unsigned*)pad, 16, 112, 112, 16, 56, 56);
    wsplit_kernel<<<cdiv_i(221184, 256), 256>>>(w2, wh + O2, wl + O2, 1728, 1728, 221184);          // 5
    conv_tc<128><<<dim3(9408, 1), 256, TC_SMEM128>>>(wh + O2, wl + O2, (unsigned*)pad, act, b2, SC, // 6 <- ncu
                                                     64, 16, 56, 56, 1728, 1728, 128, 1204224, 0);
    // pool2: act -> pad (split padded [24*128][10][30][30])
    pool_fast_kernel<2, 2, 2><<<dim3(cdiv_i(30 * 30, 256), 10, 24 * 128), 256>>>(
        act, (unsigned*)pad, 16, 56, 56, 8, 28, 28);
    wsplit_kernel<<<cdiv_i(884736, 256), 256>>>(w3a, wh + O3A, wl + O3A, 3456, 3456, 884736);
    // conv3a (fused identity pad): pad -> act (split padded [24*256][10][30][30]); zero act first
    zero_kernel<<<cdiv_i(55296000L, 256), 256>>>((unsigned*)act, 55296000);
    conv_tc<128><<<dim3(1176, 2), 256, TC_SMEM128>>>(wh + O3A, wl + O3A, (unsigned*)pad, act, b3a, 1.0f,
                                                     128, 8, 28, 28, 3456, 3456, 256, 150528, 1);
    wsplit_kernel<<<cdiv_i(1769472, 256), 256>>>(w3b, wh + O3B, wl + O3B, 6912, 6912, 1769472);
    // conv3b: act -> pad (float NCDHW)
    conv_tc<128><<<dim3(1176, 2), 256, TC_SMEM128>>>(wh + O3B, wl + O3B, (unsigned*)act, pad, b3b, SC,
                                                     256, 8, 28, 28, 6912, 6912, 256, 150528, 0);
    // pool3: pad -> act (split padded [24*256][6][16][16])
    pool_fast_kernel<2, 2, 2><<<dim3(1, 6, 24 * 256), 256>>>(
        pad, (unsigned*)act, 8, 28, 28, 4, 14, 14);
    wsplit_kernel<<<cdiv_i(3538944, 256), 256>>>(w4a, wh + O4A, wl + O4A, 6912, 6912, 3538944);
    // conv4a (fused): act -> pad (split padded [24*512][6][16][16]); zero pad first
    zero_kernel<<<cdiv_i(18874368L, 256), 256>>>((unsigned*)pad, 18874368);
    conv_tc<128><<<dim3(147, 4), 256, TC_SMEM128>>>(wh + O4A, wl + O4A, (unsigned*)act, pad, b4a, 1.0f,
                                                    256, 4, 14, 14, 6912, 6912, 512, 18816, 1);
    wsplit_kernel<<<cdiv_i(7077888, 256), 256>>>(w4b, wh + O4B, wl + O4B, 13824, 13824, 7077888);
    // conv4b: pad -> act (float)
    conv_tc<128><<<dim3(147, 4), 256, TC_SMEM128>>>(wh + O4B, wl + O4B, (unsigned*)pad, act, b4b, SC,
                                                    512, 4, 14, 14, 13824, 13824, 512, 18816, 0);
    // pool4: act -> pad (split padded [24*512][4][9][9])
    pool_fast_kernel<2, 2, 2><<<dim3(1, 4, 24 * 512), 256>>>(
        act, (unsigned*)pad, 4, 14, 14, 2, 7, 7);
    wsplit_kernel<<<cdiv_i(7077888, 256), 256>>>(w5a, wh + O5A, wl + O5A, 13824, 13824, 7077888);
    // conv5a (fused): pad -> act (split padded); zero act first
    zero_kernel<<<cdiv_i(3981312L, 256), 256>>>((unsigned*)act, 3981312);
    conv_tc<64><<<dim3(19, 8), 256, TC_SMEM64>>>(wh + O5A, wl + O5A, (unsigned*)pad, act, b5a, 1.0f,
                                                 512, 2, 7, 7, 13824, 13824, 512, 2352, 1);
    wsplit_kernel<<<cdiv_i(7077888, 256), 256>>>(w5b, wh + O5B, wl + O5B, 13824, 13824, 7077888);
    // conv5b: act -> pad (float)
    conv_tc<64><<<dim3(19, 8), 256, TC_SMEM64>>>(wh + O5B, wl + O5B, (unsigned*)act, pad, b5b, SC,
                                                 512, 2, 7, 7, 13824, 13824, 512, 2352, 0);
    // pool5 (generic, pad(0,1,1)): pad -> feat (fp32)
    pool_pad_kernel<<<dim3(1, 1, 24 * 512), 256>>>(
        pad, feat, 2, 7, 7, 2, 2, 2, 2, 2, 2, 0, 1, 1, 1, 4, 4, 0, 0);
    // fc6, fc7
    fc_tile_kernel<<<512, 256>>>(feat, fw6, fb6, fc6o, 8192, 4096, SC);
    fc_tile_kernel<<<512, 256>>>(fc6o, fw7, fb7, fc7o, 4096, 4096, SC);
    // head
    rownorm_kernel<<<24, 128>>>(fc7o, nrm, 4096);
    cost_kernel<<<144, 128>>>(fc7o, nrm, cst);
    sinkhorn_kernel<<<1, 32>>>(cst, (float*)d_out);
}